// round 4
// baseline (speedup 1.0000x reference)
#include <cuda_runtime.h>
#include <cstdint>

// Problem constants (B,V,R,C,UNITS = 16,10000,8,64,64)
#define BATCH 16
#define VN    10000
#define RN    8
#define CN    64
#define UN    64
#define NTOT  (BATCH * VN)        // 160000 nodes; 160000 % 128 == 0 -> no edge guards

#define TILE_V  128               // nodes per block (grid = 1250 exactly)
#define CN2     32                // f-chunk size (two chunks per r)
#define CSTR    132               // cols row pitch: 528B (16B-mult), 2.. keeps LDS.128 alignment
#define THREADS 256
#define VPT     16                // v's per warp strip (8 warps x 16 = 128), 64B-aligned
#define NPAIR   (VPT / 2)         // 8 f32x2 v-pairs
#define NQUAD   (VPT / 4)         // 4 16B cols loads per f

__global__ __launch_bounds__(THREADS, 4)
void graphconv_kernel(const float* __restrict__ nodes,
                      const int*   __restrict__ mapping,
                      const float* __restrict__ kern,
                      const float* __restrict__ bias,
                      float*       __restrict__ out)
{
    __shared__ __align__(16) float kS[CN2 * UN];       // [fl][u] current 32-f chunk   (8KB)
    __shared__ __align__(16) float colsS[CN2 * CSTR];  // [fl][v] gathered, v-contig (16.5KB)

    const int tid  = threadIdx.x;
    const int n0   = blockIdx.x * TILE_V;
    const int lane = tid & 31;
    const int wrp  = tid >> 5;        // 0..7
    const int u    = lane * 2;        // two adjacent units u, u+1
    const int vb   = wrp * VPT;       // 16-v strip: 64B aligned ✓

    // acc0[i]: (v=vb+2i, vb+2i+1) @ u ; acc1[i]: same @ u+1
    unsigned long long acc0[NPAIR], acc1[NPAIR];
    #pragma unroll
    for (int i = 0; i < NPAIR; i++) { acc0[i] = 0ULL; acc1[i] = 0ULL; }

    const unsigned colsB = (unsigned)__cvta_generic_to_shared(colsS);
    const unsigned kB    = (unsigned)__cvta_generic_to_shared(kS);

    for (int chunk = 0; chunk < RN * 2; chunk++) {
        const int r    = chunk >> 1;
        const int half = chunk & 1;          // channel half: c in [32*half, 32*half+32)
        __syncthreads();                     // previous chunk fully consumed

        // --- stage kernel chunk rows f = r*64 + half*32 + [0,32) ---
        {
            const float4* src = reinterpret_cast<const float4*>(kern + (r * CN + half * CN2) * UN);
            float4*       dst = reinterpret_cast<float4*>(kS);
            #pragma unroll
            for (int i = 0; i < (CN2 * UN / 4) / THREADS; i++)   // 2 iters
                dst[tid + i * THREADS] = src[tid + i * THREADS];
        }

        // --- gather: 128 nodes x 32 channels, transposed into [fl][v] ---
        {
            const int c   = tid & 31;        // local f within chunk
            const int vl0 = tid >> 5;        // 0..7
            #pragma unroll
            for (int it = 0; it < TILE_V / 8; it++) {            // 16 iters
                const int vl = vl0 + it * 8;
                const int n  = n0 + vl;
                const int b  = n / VN;                           // IMAD const-div
                const int m  = mapping[n * RN + r];              // warp-uniform LDG
                float val = 0.0f;
                if (m >= 0)
                    val = nodes[((b * VN + m) * CN) + half * CN2 + c];  // 128B/warp coalesced
                colsS[c * CSTR + vl] = val;                      // 4-way STS conflict (cheap phase)
            }
        }
        __syncthreads();

        // --- compute: rank-32 update, 16v x 2u per thread ---
        #pragma unroll 4
        for (int f = 0; f < CN2; f++) {
            // kernel pair (k[f][u], k[f][u+1]) via one LDS.64 (consecutive lanes -> no conflict)
            unsigned long long kpair;
            asm("ld.shared.b64 %0, [%1];" : "=l"(kpair) : "r"(kB + (f * UN + u) * 4u));
            unsigned klo, khi;
            asm("mov.b64 {%0, %1}, %2;" : "=r"(klo), "=r"(khi) : "l"(kpair));
            unsigned long long kk0, kk1;
            asm("mov.b64 %0, {%1, %1};" : "=l"(kk0) : "r"(klo));
            asm("mov.b64 %0, {%1, %1};" : "=l"(kk1) : "r"(khi));

            const unsigned cbase = colsB + (f * CSTR + vb) * 4u;
            #pragma unroll
            for (int q = 0; q < NQUAD; q++) {
                // 16B broadcast load -> two f32x2 pairs, no repacking
                unsigned long long c0, c1;
                asm("ld.shared.v2.u64 {%0, %1}, [%2];"
                    : "=l"(c0), "=l"(c1) : "r"(cbase + q * 16u));
                asm("fma.rn.f32x2 %0, %1, %2, %3;"
                    : "=l"(acc0[2*q])   : "l"(c0), "l"(kk0), "l"(acc0[2*q]));
                asm("fma.rn.f32x2 %0, %1, %2, %3;"
                    : "=l"(acc1[2*q])   : "l"(c0), "l"(kk1), "l"(acc1[2*q]));
                asm("fma.rn.f32x2 %0, %1, %2, %3;"
                    : "=l"(acc0[2*q+1]) : "l"(c1), "l"(kk0), "l"(acc0[2*q+1]));
                asm("fma.rn.f32x2 %0, %1, %2, %3;"
                    : "=l"(acc1[2*q+1]) : "l"(c1), "l"(kk1), "l"(acc1[2*q+1]));
            }
        }
    }

    // --- epilogue: bias + ReLU + packed STG.64 (exact tiling, no guards) ---
    const float bu0 = bias[u];
    const float bu1 = bias[u + 1];
    #pragma unroll
    for (int i = 0; i < NPAIR; i++) {
        unsigned a0, a1, b0, b1;
        asm("mov.b64 {%0, %1}, %2;" : "=r"(a0), "=r"(a1) : "l"(acc0[i]));  // u   @ v, v+1
        asm("mov.b64 {%0, %1}, %2;" : "=r"(b0), "=r"(b1) : "l"(acc1[i]));  // u+1 @ v, v+1
        const int n = n0 + vb + 2 * i;
        float2 o0, o1;
        o0.x = fmaxf(__uint_as_float(a0) + bu0, 0.0f);
        o0.y = fmaxf(__uint_as_float(b0) + bu1, 0.0f);
        o1.x = fmaxf(__uint_as_float(a1) + bu0, 0.0f);
        o1.y = fmaxf(__uint_as_float(b1) + bu1, 0.0f);
        *reinterpret_cast<float2*>(out + (size_t)n       * UN + u) = o0;   // 256B/warp coalesced
        *reinterpret_cast<float2*>(out + (size_t)(n + 1) * UN + u) = o1;
    }
}

extern "C" void kernel_launch(void* const* d_in, const int* in_sizes, int n_in,
                              void* d_out, int out_size)
{
    const float* nodes   = (const float*)d_in[0];   // [16,10000,64] f32
    const int*   mapping = (const int*)  d_in[1];   // [16,10000,8]  i32
    const float* kern    = (const float*)d_in[2];   // [512,64]      f32
    const float* bias    = (const float*)d_in[3];   // [64]          f32
    float*       out     = (float*)d_out;           // [16,10000,64] f32

    const int grid = NTOT / TILE_V;                 // 1250 blocks, exact
    graphconv_kernel<<<grid, THREADS>>>(nodes, mapping, kern, bias, out);
}

// round 6
// speedup vs baseline: 1.0409x; 1.0409x over previous
#include <cuda_runtime.h>
#include <cstdint>

// Problem constants (B,V,R,C,UNITS = 16,10000,8,64,64)
#define BATCH 16
#define VN    10000
#define RN    8
#define CN    64
#define UN    64
#define NTOT  (BATCH * VN)        // 160000; % 128 == 0 -> no edge guards

#define TILE_V  128               // nodes per block (grid = 1250 exactly)
#define CN2     32                // f-chunk size (two chunks per r)
#define CSTR    132               // cols pitch in floats: 528B, keeps 16B alignment
#define THREADS 256

__global__ __launch_bounds__(THREADS, 4)
void graphconv_kernel(const float* __restrict__ nodes,
                      const int*   __restrict__ mapping,
                      const float* __restrict__ kern,
                      const float* __restrict__ bias,
                      float*       __restrict__ out)
{
    __shared__ __align__(16) float kS[CN2 * UN];       // [fl][u]  8KB
    __shared__ __align__(16) float colsS[CN2 * CSTR];  // [fl][v]  16.5KB

    const int tid  = threadIdx.x;
    const int n0   = blockIdx.x * TILE_V;
    const int lane = tid & 31;
    const int wrp  = tid >> 5;          // 0..7
    const int wv   = wrp & 3;           // warp v-strip (32 v each)
    const int wu   = wrp >> 2;          // warp u-strip (32 u each)
    const int vg   = lane >> 3;         // 0..3  v-group within warp
    const int ug   = lane & 7;          // 0..7  u-group within warp
    const int vb   = wv * 32 + vg * 8;  // thread v-base (8 v, 32B-aligned)
    const int ub   = wu * 32 + ug * 4;  // thread u-base (4 u, 16B-aligned)

    // acc[vi][uj]: packed f32x2 over v-pair (vb+2vi, vb+2vi+1) at unit ub+uj
    unsigned long long acc[4][4];
    #pragma unroll
    for (int i = 0; i < 4; i++)
        #pragma unroll
        for (int j = 0; j < 4; j++) acc[i][j] = 0ULL;

    const unsigned colsB = (unsigned)__cvta_generic_to_shared(colsS);
    const unsigned kB    = (unsigned)__cvta_generic_to_shared(kS);

    for (int chunk = 0; chunk < RN * 2; chunk++) {
        const int r    = chunk >> 1;
        const int half = chunk & 1;     // channel half within r
        __syncthreads();                // previous chunk fully consumed

        // --- stage kernel chunk rows f = r*64 + half*32 + [0,32) ---
        {
            const float4* src = reinterpret_cast<const float4*>(kern + (r * CN + half * CN2) * UN);
            float4*       dst = reinterpret_cast<float4*>(kS);
            #pragma unroll
            for (int i = 0; i < (CN2 * UN / 4) / THREADS; i++)   // 2 iters
                dst[tid + i * THREADS] = src[tid + i * THREADS];
        }

        // --- gather: 128 nodes x 32 channels, transposed into [fl][v] ---
        {
            const int c   = tid & 31;    // local channel
            const int vl0 = tid >> 5;    // 0..7
            #pragma unroll
            for (int it = 0; it < TILE_V / 8; it++) {            // 16 iters
                const int vl = vl0 + it * 8;
                const int n  = n0 + vl;
                const int b  = n / VN;                           // IMAD const-div
                const int m  = mapping[n * RN + r];              // warp-uniform LDG
                float val = 0.0f;
                if (m >= 0)
                    val = nodes[((b * VN + m) * CN) + half * CN2 + c];  // 128B/warp coalesced
                colsS[c * CSTR + vl] = val;                      // 4-way STS (staging phase)
            }
        }
        __syncthreads();

        // --- compute: rank-32 update, 8v x 4u register tile per thread ---
        unsigned kAddr = kB    + (unsigned)ub * 4u;
        unsigned cAddr = colsB + (unsigned)vb * 4u;
        #pragma unroll 4
        for (int f = 0; f < CN2; f++) {
            // kernel quad (k[f][ub..ub+3]): 8 ug-groups x 16B = 128B, conflict-free, 1 wf
            float k0, k1, k2, k3;
            asm("ld.shared.v4.f32 {%0, %1, %2, %3}, [%4];"
                : "=f"(k0), "=f"(k1), "=f"(k2), "=f"(k3) : "r"(kAddr));
            unsigned long long kk[4];
            asm("mov.b64 %0, {%1, %1};" : "=l"(kk[0]) : "f"(k0));
            asm("mov.b64 %0, {%1, %1};" : "=l"(kk[1]) : "f"(k1));
            asm("mov.b64 %0, {%1, %1};" : "=l"(kk[2]) : "f"(k2));
            asm("mov.b64 %0, {%1, %1};" : "=l"(kk[3]) : "f"(k3));

            // cols: 8 v as 4 f32x2 pairs via 2x LDS.128 (4 vg-groups x 16B, 32B apart -> 1 wf each)
            unsigned long long cp0, cp1, cp2, cp3;
            asm("ld.shared.v2.u64 {%0, %1}, [%2];"      : "=l"(cp0), "=l"(cp1) : "r"(cAddr));
            asm("ld.shared.v2.u64 {%0, %1}, [%2+16];"   : "=l"(cp2), "=l"(cp3) : "r"(cAddr));

            #pragma unroll
            for (int j = 0; j < 4; j++) {
                asm("fma.rn.f32x2 %0, %1, %2, %3;" : "=l"(acc[0][j]) : "l"(cp0), "l"(kk[j]), "l"(acc[0][j]));
                asm("fma.rn.f32x2 %0, %1, %2, %3;" : "=l"(acc[1][j]) : "l"(cp1), "l"(kk[j]), "l"(acc[1][j]));
                asm("fma.rn.f32x2 %0, %1, %2, %3;" : "=l"(acc[2][j]) : "l"(cp2), "l"(kk[j]), "l"(acc[2][j]));
                asm("fma.rn.f32x2 %0, %1, %2, %3;" : "=l"(acc[3][j]) : "l"(cp3), "l"(kk[j]), "l"(acc[3][j]));
            }
            kAddr += UN * 4u;
            cAddr += CSTR * 4u;
        }
    }

    // --- epilogue: bias + ReLU + STG.128 (lanes ug0..7 -> 128B coalesced runs) ---
    const float4 b4 = *reinterpret_cast<const float4*>(bias + ub);
    #pragma unroll
    for (int vi = 0; vi < 4; vi++) {
        float lo[4], hi[4];
        #pragma unroll
        for (int j = 0; j < 4; j++) {
            unsigned l, h;
            asm("mov.b64 {%0, %1}, %2;" : "=r"(l), "=r"(h) : "l"(acc[vi][j]));
            lo[j] = __uint_as_float(l);
            hi[j] = __uint_as_float(h);
        }
        const int n = n0 + vb + 2 * vi;
        float4 o0, o1;
        o0.x = fmaxf(lo[0] + b4.x, 0.0f); o0.y = fmaxf(lo[1] + b4.y, 0.0f);
        o0.z = fmaxf(lo[2] + b4.z, 0.0f); o0.w = fmaxf(lo[3] + b4.w, 0.0f);
        o1.x = fmaxf(hi[0] + b4.x, 0.0f); o1.y = fmaxf(hi[1] + b4.y, 0.0f);
        o1.z = fmaxf(hi[2] + b4.z, 0.0f); o1.w = fmaxf(hi[3] + b4.w, 0.0f);
        *reinterpret_cast<float4*>(out + (size_t)n       * UN + ub) = o0;
        *reinterpret_cast<float4*>(out + (size_t)(n + 1) * UN + ub) = o1;
    }
}

extern "C" void kernel_launch(void* const* d_in, const int* in_sizes, int n_in,
                              void* d_out, int out_size)
{
    const float* nodes   = (const float*)d_in[0];   // [16,10000,64] f32
    const int*   mapping = (const int*)  d_in[1];   // [16,10000,8]  i32
    const float* kern    = (const float*)d_in[2];   // [512,64]      f32
    const float* bias    = (const float*)d_in[3];   // [64]          f32
    float*       out     = (float*)d_out;           // [16,10000,64] f32

    const int grid = NTOT / TILE_V;                 // 1250 blocks, exact
    graphconv_kernel<<<grid, THREADS>>>(nodes, mapping, kern, bias, out);
}